// round 15
// baseline (speedup 1.0000x reference)
#include <cuda_runtime.h>
#include <cstdint>

#define BB 8
#define NN 262144
#define KK 256
#define DD 16
#define CAP 2048
#define MMAX 1024
#define CPE 18                  // chunks per event
#define GRID (CPE * BB)         // 144 blocks, all resident in wave 1
#define NTHR 1024
#define PB_CH 14564             // ceil(NN/CPE), divisible by 4
#define RCH 64                  // rep j-chunk size (16 chunks x 8 events = 128 blocks)

// ---------------- scratch (device globals; zero == reset state) ----------------
__device__ float  g_sum_f [BB][KK];
__device__ int    g_cnt_cp[BB][KK];
__device__ int    g_inst  [BB][KK];
__device__ int    g_first [BB][KK];   // stores max(NN - li); 0 == no CP
__device__ float  g_sd2   [BB][KK];
__device__ int    g_Mv    [BB];
__device__ int    g_cplist[BB][CAP];
__device__ float  g_scal_f[BB][4];
__device__ int    g_scal_i[BB][2];    // 0: n_cp(all), 1: n_bg
__device__ float  g_rep   [BB];

// grid barrier state (gen grows monotonically across replays -> replay-safe)
__device__ unsigned          g_bar_cnt[2];
__device__ volatile unsigned g_bar_gen[2];

__device__ __forceinline__ void grid_barrier(int idx) {
    __syncthreads();
    if (threadIdx.x == 0) {
        __threadfence();
        const unsigned my = g_bar_gen[idx];
        const unsigned arr = atomicAdd(&g_bar_cnt[idx], 1u);
        if (arr == GRID - 1) {
            g_bar_cnt[idx] = 0;
            __threadfence();
            g_bar_gen[idx] = my + 1;
        } else {
            while (g_bar_gen[idx] == my) { }
        }
        __threadfence();
    }
    __syncthreads();
}

// fast sigmoid + softplus: 2 MUFU + FMA-pipe Newton rcp (seed valid on u in (1,2])
__device__ __forceinline__ void fast_sig_sp(float x, float& p, float& ce0) {
    const float t = __expf(-fabsf(x));
    const float u = 1.f + t;
    float y = __fmaf_rn(u, -0.47058824f, 1.4117647f);
    y = y * __fmaf_rn(-u, y, 2.f);
    y = y * __fmaf_rn(-u, y, 2.f);
    ce0 = fmaxf(x, 0.f) + __logf(u);
    p   = (x >= 0.f) ? y : t * y;
}

__global__ void __launch_bounds__(NTHR) fused_all_kernel(
    const float* __restrict__ beta,
    const float* __restrict__ embed,
    const int* __restrict__ sid,
    const int* __restrict__ cp,
    float* __restrict__ out)
{
    const int blk = blockIdx.x;
    const int tid = threadIdx.x;
    const int b     = blk / CPE;
    const int chunk = blk % CPE;
    const size_t ev_base = (size_t)b * NN;
    const int start = chunk * PB_CH;
    const int end   = min(start + PB_CH, NN);

    __shared__ float s_f[KK];
    __shared__ int   s_cnt[KK];
    __shared__ int   s_first[KK];
    __shared__ float s_sc[4];
    __shared__ int   s_si[2];
    __shared__ float4             sA[KK][4];      // 16 KB (phase 2)
    __shared__ unsigned long long spack[KK];      // 2 KB  (phase 2)
    __shared__ unsigned char      shc[KK];
    __shared__ int   sidx[CAP];                   // 8 KB  (phase 3)
    __shared__ float sj[RCH * DD];                // 4 KB  (phase 3)
    __shared__ float red[32];

    // ================= PHASE 1: pass_a =================
    if (tid < KK) { s_f[tid] = 0.f; s_cnt[tid] = 0; s_first[tid] = 0; }
    if (tid < 4) s_sc[tid] = 0.f;
    if (tid < 2) s_si[tid] = 0;
    __syncthreads();

    {
        float ce0n = 0.f, bg = 0.f, pm = 0.f, nm = 0.f;
        int ncp = 0, nbg = 0;

        for (int base = start + tid * 4; base < end; base += NTHR * 4) {
            const int4   s4 = *reinterpret_cast<const int4*>(sid + ev_base + base);
            const int4   c4 = *reinterpret_cast<const int4*>(cp  + ev_base + base);
            const float4 x4 = *reinterpret_cast<const float4*>(beta + ev_base + base);

            const int   sv[4] = {s4.x, s4.y, s4.z, s4.w};
            const int   cv[4] = {c4.x, c4.y, c4.z, c4.w};
            const float xv[4] = {x4.x, x4.y, x4.z, x4.w};

            #pragma unroll
            for (int j = 0; j < 4; j++) {
                const int   s = sv[j];
                const float x = xv[j];
                float p, ce0;
                fast_sig_sp(x, p, ce0);

                if (cv[j]) {
                    ncp++;
                    pm += fmaxf(0.8f - p, 0.f);
                    if (s >= 0) {
                        const float om = 1.f - p;
                        atomicAdd(&s_f[s], 0.75f * om * om * (ce0 - x));
                        atomicAdd(&s_cnt[s], 1);
                        atomicMax(&s_first[s], NN - (base + j));
                        int pos = atomicAdd(&g_Mv[b], 1);
                        if (pos < CAP) g_cplist[b][pos] = base + j;
                    }
                } else {
                    ce0n += ce0;
                    nm += fmaxf(p - 0.2f, 0.f);
                }
                if (s == -1) { nbg++; bg += ce0; }
            }
        }

        atomicAdd(&s_sc[0], ce0n);
        atomicAdd(&s_sc[1], bg);
        atomicAdd(&s_sc[2], pm);
        atomicAdd(&s_sc[3], nm);
        atomicAdd(&s_si[0], ncp);
        atomicAdd(&s_si[1], nbg);
    }
    __syncthreads();

    if (tid < KK) {
        if (s_f[tid] != 0.f) atomicAdd(&g_sum_f[b][tid], s_f[tid]);
        if (s_cnt[tid])      atomicAdd(&g_cnt_cp[b][tid], s_cnt[tid]);
        if (s_first[tid])    atomicMax(&g_first[b][tid], s_first[tid]);
    }
    if (tid < 4) atomicAdd(&g_scal_f[b][tid], s_sc[tid]);
    if (tid < 2) atomicAdd(&g_scal_i[b][tid], s_si[tid]);

    grid_barrier(0);

    // ================= PHASE 2: pass_b =================
    if (tid < KK) {
        spack[tid] = 0ull;
        shc[tid] = (__ldcg(&g_cnt_cp[b][tid]) > 0) ? 1 : 0;
    }
    // anchor gather: NTHR = 1024 covers KK*4 exactly
    {
        const int k = tid >> 2, q = tid & 3;
        const int val = __ldcg(&g_first[b][k]);
        float4 v = make_float4(0.f, 0.f, 0.f, 0.f);
        if (val > 0)
            v = reinterpret_cast<const float4*>(embed + (ev_base + (NN - val)) * DD)[q];
        sA[k][q] = v;
    }
    __syncthreads();

    #pragma unroll 2
    for (int row = start + tid; row < end; row += NTHR) {
        const int s = sid[ev_base + row];
        if (s >= 0 && shc[s]) {
            const float4* e = reinterpret_cast<const float4*>(embed + (ev_base + row) * DD);
            const float4 e0 = e[0], e1 = e[1], e2 = e[2], e3 = e[3];
            const float4 a0 = sA[s][0], a1 = sA[s][1], a2 = sA[s][2], a3 = sA[s][3];
            float d2 = 0.f;
            d2 = __fmaf_rn(e0.x - a0.x, e0.x - a0.x, d2);
            d2 = __fmaf_rn(e0.y - a0.y, e0.y - a0.y, d2);
            d2 = __fmaf_rn(e0.z - a0.z, e0.z - a0.z, d2);
            d2 = __fmaf_rn(e0.w - a0.w, e0.w - a0.w, d2);
            d2 = __fmaf_rn(e1.x - a1.x, e1.x - a1.x, d2);
            d2 = __fmaf_rn(e1.y - a1.y, e1.y - a1.y, d2);
            d2 = __fmaf_rn(e1.z - a1.z, e1.z - a1.z, d2);
            d2 = __fmaf_rn(e1.w - a1.w, e1.w - a1.w, d2);
            d2 = __fmaf_rn(e2.x - a2.x, e2.x - a2.x, d2);
            d2 = __fmaf_rn(e2.y - a2.y, e2.y - a2.y, d2);
            d2 = __fmaf_rn(e2.z - a2.z, e2.z - a2.z, d2);
            d2 = __fmaf_rn(e2.w - a2.w, e2.w - a2.w, d2);
            d2 = __fmaf_rn(e3.x - a3.x, e3.x - a3.x, d2);
            d2 = __fmaf_rn(e3.y - a3.y, e3.y - a3.y, d2);
            d2 = __fmaf_rn(e3.z - a3.z, e3.z - a3.z, d2);
            d2 = __fmaf_rn(e3.w - a3.w, e3.w - a3.w, d2);
            atomicAdd(&spack[s], (1ull << 44) + __float2ull_rn(d2 * 1048576.f));
        }
    }
    __syncthreads();
    if (tid < KK) {
        const unsigned long long v = spack[tid];
        if (v) {
            atomicAdd(&g_inst[b][tid], (int)(v >> 44));
            const float ds = (float)(v & ((1ull << 44) - 1ull)) * (1.f / 1048576.f);
            if (ds != 0.f) atomicAdd(&g_sd2[b][tid], ds);
        }
    }

    // ================= PHASE 3: repulsion (blocks 0..127) =================
    if (blk < 128) {
        const int rb = blk >> 4;                 // event
        const int j0 = (blk & 15) * RCH;
        const int Mv   = __ldcg(&g_Mv[rb]);
        const int msel = min(Mv, MMAX);
        if (j0 < msel) {
            const int cnt = min(RCH, msel - j0);
            const int mcol = min(Mv, CAP);
            for (int i = tid; i < CAP; i += NTHR)
                sidx[i] = (i < mcol) ? __ldcg(&g_cplist[rb][i]) : 0x7fffffff;
            __syncthreads();

            if (Mv > MMAX) {   // statistically never; correctness fallback
                for (int ksz = 2; ksz <= CAP; ksz <<= 1) {
                    for (int j = ksz >> 1; j > 0; j >>= 1) {
                        for (int i = tid; i < CAP; i += NTHR) {
                            int ixj = i ^ j;
                            if (ixj > i) {
                                bool up = ((i & ksz) == 0);
                                int a = sidx[i], c = sidx[ixj];
                                if ((a > c) == up) { sidx[i] = c; sidx[ixj] = a; }
                            }
                        }
                        __syncthreads();
                    }
                }
            }

            const size_t rev_base = (size_t)rb * NN;
            for (int t = tid; t < cnt * 4; t += NTHR) {
                const int j = t >> 2, qq = t & 3;
                reinterpret_cast<float4*>(sj)[t] =
                    reinterpret_cast<const float4*>(embed + (rev_base + sidx[j0 + j]) * DD)[qq];
            }
            __syncthreads();

            float acc = 0.f;
            for (int i = tid; i < msel; i += NTHR) {
                float myE[DD];
                const float4* er = reinterpret_cast<const float4*>(embed + (rev_base + sidx[i]) * DD);
                #pragma unroll
                for (int qq = 0; qq < 4; qq++) {
                    const float4 v = er[qq];
                    myE[qq * 4 + 0] = v.x; myE[qq * 4 + 1] = v.y;
                    myE[qq * 4 + 2] = v.z; myE[qq * 4 + 3] = v.w;
                }
                #pragma unroll 2
                for (int j = 0; j < cnt; j++) {
                    float d2 = 0.f;
                    #pragma unroll
                    for (int d = 0; d < DD; d++) {
                        const float df = myE[d] - sj[j * DD + d];
                        d2 = __fmaf_rn(df, df, d2);
                    }
                    acc += __expf(-d2);
                }
            }

            #pragma unroll
            for (int off = 16; off; off >>= 1) acc += __shfl_down_sync(0xffffffff, acc, off);
            if ((tid & 31) == 0) red[tid >> 5] = acc;
            __syncthreads();
            if (tid == 0) {
                float tot = 0.f;
                #pragma unroll
                for (int w = 0; w < 32; w++) tot += red[w];
                atomicAdd(&g_rep[rb], tot);
            }
        }
    }

    grid_barrier(1);

    // ================= PHASE 4: finalize + reset (block 0 only) =================
    if (blk == 0) {
        const int lane = tid & 31;
        const int wid  = tid >> 5;

        __shared__ float s_loss[BB];
        __shared__ int   s_ok[BB];

        if (wid < BB) {
            const int e = wid;
            int   c[8], inst[8];
            float sf[8], sd[8];
            #pragma unroll
            for (int i = 0; i < 8; i++) {
                const int k = lane + i * 32;
                c[i]    = __ldcg(&g_cnt_cp[e][k]);
                inst[i] = __ldcg(&g_inst[e][k]);
                sf[i]   = __ldcg(&g_sum_f[e][k]);
                sd[i]   = __ldcg(&g_sd2[e][k]);
            }

            float w = 0.f, wf = 0.f, at = 0.f;
            #pragma unroll
            for (int i = 0; i < 8; i++) {
                if (c[i] > 0) {
                    const float fw = (float)inst[i];
                    w  += fw;
                    wf += fw * sf[i] / fmaxf((float)c[i], 1.f);
                    at += sd[i] / fmaxf((float)inst[i], 1.f);
                }
            }
            #pragma unroll
            for (int off = 16; off; off >>= 1) {
                w  += __shfl_down_sync(0xffffffff, w,  off);
                wf += __shfl_down_sync(0xffffffff, wf, off);
                at += __shfl_down_sync(0xffffffff, at, off);
            }

            if (lane == 0) {
                const float pos_bce = wf / fmaxf(w, 1.f);

                const float n_cp  = (float)__ldcg(&g_scal_i[e][0]);
                const float n_bg  = (float)__ldcg(&g_scal_i[e][1]);
                const float n_ncp = (float)NN - n_cp;
                const float n_val = (float)NN - n_bg;

                const float f0 = __ldcg(&g_scal_f[e][0]);
                const float f1 = __ldcg(&g_scal_f[e][1]);
                const float f2 = __ldcg(&g_scal_f[e][2]);
                const float f3 = __ldcg(&g_scal_f[e][3]);

                const float neg_bce    = (n_ncp > 0.f) ? f0 / fmaxf(n_ncp, 1.f) : 0.f;
                const float bg_bce     = (n_bg  > 0.f) ? f1 / fmaxf(n_bg,  1.f) : 0.f;
                const float pos_margin = f2 / fmaxf(n_cp, 1.f);
                const float neg_margin = (n_ncp > 0.f) ? f3 / fmaxf(n_ncp, 1.f) : 0.f;

                const float beta_loss = 10.f * pos_bce + 3.f * neg_bce + 6.f * bg_bce
                                      + 10.f * (pos_margin + neg_margin);

                const int   Mv = __ldcg(&g_Mv[e]);
                const float fM = (float)Mv;
                const float rep_term = (Mv > 1) ? __ldcg(&g_rep[e]) / fmaxf(fM * fM, 1.f) : 0.f;

                s_loss[e] = beta_loss + at + rep_term;
                s_ok[e]   = (n_val > 0.f) && (Mv > 0);
            }
        }
        __syncthreads();

        if (tid == 0) {
            float total = 0.f, cnt = 0.f;
            #pragma unroll
            for (int e = 0; e < BB; e++)
                if (s_ok[e]) { total += s_loss[e]; cnt += 1.f; }
            out[0] = (cnt > 0.f) ? total / fmaxf(cnt, 1.f) : 0.f;
        }
        __syncthreads();

        // reset all scratch so the graph replays deterministically
        for (int t = tid; t < BB * KK; t += NTHR) {
            const int e = t >> 8, k = t & 255;
            g_sum_f[e][k]  = 0.f;
            g_cnt_cp[e][k] = 0;
            g_inst[e][k]   = 0;
            g_first[e][k]  = 0;
            g_sd2[e][k]    = 0.f;
        }
        if (tid < BB) {
            g_Mv[tid]  = 0;
            g_rep[tid] = 0.f;
            #pragma unroll
            for (int j = 0; j < 4; j++) g_scal_f[tid][j] = 0.f;
            g_scal_i[tid][0] = 0; g_scal_i[tid][1] = 0;
        }
    }
}

// ---------------- launch: ONE persistent kernel ----------------
extern "C" void kernel_launch(void* const* d_in, const int* in_sizes, int n_in,
                              void* d_out, int out_size)
{
    (void)in_sizes; (void)n_in; (void)out_size;
    const float* beta  = (const float*)d_in[0];
    const float* embed = (const float*)d_in[1];
    const int*   sid   = (const int*)d_in[2];
    const int*   cp    = (const int*)d_in[3];

    fused_all_kernel<<<GRID, NTHR>>>(beta, embed, sid, cp, (float*)d_out);
}

// round 16
// speedup vs baseline: 1.2203x; 1.2203x over previous
#include <cuda_runtime.h>
#include <cstdint>

#define BB 8
#define NN 262144
#define KK 256
#define DD 16
#define CAP 2048
#define MMAX 1024
#define NTHR 512
#define GRID 296               // 2 CTAs/SM x 148 SMs, all wave-1 resident
#define CPE1 37                // phase-1 chunks per event (37*8 = 296)
#define CH1 7088               // ceil(NN/37) rounded to mult of 4
#define PB_BLOCKS 280          // phase-2 blocks (35 chunks x 8 events)
#define CPE2 35
#define CH2 7492               // ceil(NN/35) rounded to mult of 4
#define RJT 64                 // rep j-tile size

// ---------------- scratch (device globals; zero == reset state) ----------------
__device__ float  g_sum_f [BB][KK];
__device__ int    g_cnt_cp[BB][KK];
__device__ int    g_inst  [BB][KK];
__device__ int    g_first [BB][KK];   // stores max(NN - li); 0 == no CP
__device__ float  g_sd2   [BB][KK];
__device__ int    g_Mv    [BB];
__device__ int    g_cplist[BB][CAP];
__device__ float  g_scal_f[BB][4];
__device__ int    g_scal_i[BB][2];    // 0: n_cp(all), 1: n_bg
__device__ float  g_rep   [BB];

// grid barrier state (gen grows monotonically across replays -> replay-safe)
__device__ unsigned          g_bar_cnt[2];
__device__ volatile unsigned g_bar_gen[2];

__device__ __forceinline__ void grid_barrier(int idx) {
    __syncthreads();
    if (threadIdx.x == 0) {
        __threadfence();
        const unsigned my = g_bar_gen[idx];
        const unsigned arr = atomicAdd(&g_bar_cnt[idx], 1u);
        if (arr == GRID - 1) {
            g_bar_cnt[idx] = 0;
            __threadfence();
            g_bar_gen[idx] = my + 1;
        } else {
            while (g_bar_gen[idx] == my) { }
        }
        __threadfence();
    }
    __syncthreads();
}

// fast sigmoid + softplus: 2 MUFU + FMA-pipe Newton rcp (seed valid on u in (1,2])
__device__ __forceinline__ void fast_sig_sp(float x, float& p, float& ce0) {
    const float t = __expf(-fabsf(x));
    const float u = 1.f + t;
    float y = __fmaf_rn(u, -0.47058824f, 1.4117647f);
    y = y * __fmaf_rn(-u, y, 2.f);
    y = y * __fmaf_rn(-u, y, 2.f);
    ce0 = fmaxf(x, 0.f) + __logf(u);
    p   = (x >= 0.f) ? y : t * y;
}

__global__ void __launch_bounds__(NTHR, 2) fused_all_kernel(
    const float* __restrict__ beta,
    const float* __restrict__ embed,
    const int* __restrict__ sid,
    const int* __restrict__ cp,
    float* __restrict__ out)
{
    const int blk = blockIdx.x;
    const int tid = threadIdx.x;

    __shared__ float s_f[KK];
    __shared__ int   s_cnt[KK];
    __shared__ int   s_first[KK];
    __shared__ float s_sc[4];
    __shared__ int   s_si[2];
    __shared__ float4             sA[KK][4];      // 16 KB (phase 2)
    __shared__ unsigned long long spack[KK];      // 2 KB  (phase 2)
    __shared__ unsigned char      shc[KK];
    __shared__ int   sidx[CAP];                   // 8 KB  (phase 3)
    __shared__ float sj[RJT * DD];                // 4 KB  (phase 3)
    __shared__ float red[16];

    // ================= PHASE 1: pass_a (all 296 blocks, CPE1=37 chunks/event) ========
    {
        const int b1     = blk / CPE1;
        const int chunk1 = blk % CPE1;
        const size_t eb1 = (size_t)b1 * NN;
        const int start1 = chunk1 * CH1;
        const int end1   = min(start1 + CH1, NN);

        if (tid < KK) { s_f[tid] = 0.f; s_cnt[tid] = 0; s_first[tid] = 0; }
        if (tid < 4) s_sc[tid] = 0.f;
        if (tid < 2) s_si[tid] = 0;
        __syncthreads();

        float ce0n = 0.f, bg = 0.f, pm = 0.f, nm = 0.f;
        int ncp = 0, nbg = 0;

        for (int base = start1 + tid * 4; base < end1; base += NTHR * 4) {
            const int4   s4 = *reinterpret_cast<const int4*>(sid + eb1 + base);
            const int4   c4 = *reinterpret_cast<const int4*>(cp  + eb1 + base);
            const float4 x4 = *reinterpret_cast<const float4*>(beta + eb1 + base);

            const int   sv[4] = {s4.x, s4.y, s4.z, s4.w};
            const int   cv[4] = {c4.x, c4.y, c4.z, c4.w};
            const float xv[4] = {x4.x, x4.y, x4.z, x4.w};

            #pragma unroll
            for (int j = 0; j < 4; j++) {
                const int   s = sv[j];
                const float x = xv[j];
                float p, ce0;
                fast_sig_sp(x, p, ce0);

                if (cv[j]) {
                    ncp++;
                    pm += fmaxf(0.8f - p, 0.f);
                    if (s >= 0) {
                        const float om = 1.f - p;
                        atomicAdd(&s_f[s], 0.75f * om * om * (ce0 - x));
                        atomicAdd(&s_cnt[s], 1);
                        atomicMax(&s_first[s], NN - (base + j));
                        int pos = atomicAdd(&g_Mv[b1], 1);
                        if (pos < CAP) g_cplist[b1][pos] = base + j;
                    }
                } else {
                    ce0n += ce0;
                    nm += fmaxf(p - 0.2f, 0.f);
                }
                if (s == -1) { nbg++; bg += ce0; }
            }
        }

        atomicAdd(&s_sc[0], ce0n);
        atomicAdd(&s_sc[1], bg);
        atomicAdd(&s_sc[2], pm);
        atomicAdd(&s_sc[3], nm);
        atomicAdd(&s_si[0], ncp);
        atomicAdd(&s_si[1], nbg);
        __syncthreads();

        if (tid < KK) {
            if (s_f[tid] != 0.f) atomicAdd(&g_sum_f[b1][tid], s_f[tid]);
            if (s_cnt[tid])      atomicAdd(&g_cnt_cp[b1][tid], s_cnt[tid]);
            if (s_first[tid])    atomicMax(&g_first[b1][tid], s_first[tid]);
        }
        if (tid < 4) atomicAdd(&g_scal_f[b1][tid], s_sc[tid]);
        if (tid < 2) atomicAdd(&g_scal_i[b1][tid], s_si[tid]);
    }

    grid_barrier(0);

    if (blk < PB_BLOCKS) {
        // ================= PHASE 2: pass_b (blocks 0..279, CPE2=35 chunks/event) =====
        const int b2     = blk / CPE2;
        const int chunk2 = blk % CPE2;
        const size_t eb2 = (size_t)b2 * NN;
        const int start2 = chunk2 * CH2;
        const int end2   = min(start2 + CH2, NN);

        if (tid < KK) {
            spack[tid] = 0ull;
            shc[tid] = (__ldcg(&g_cnt_cp[b2][tid]) > 0) ? 1 : 0;
        }
        #pragma unroll
        for (int i = tid; i < KK * 4; i += NTHR) {
            const int k = i >> 2, q = i & 3;
            const int val = __ldcg(&g_first[b2][k]);
            float4 v = make_float4(0.f, 0.f, 0.f, 0.f);
            if (val > 0)
                v = reinterpret_cast<const float4*>(embed + (eb2 + (NN - val)) * DD)[q];
            sA[k][q] = v;
        }
        __syncthreads();

        #pragma unroll 2
        for (int row = start2 + tid; row < end2; row += NTHR) {
            const int s = sid[eb2 + row];
            if (s >= 0 && shc[s]) {
                const float4* e = reinterpret_cast<const float4*>(embed + (eb2 + row) * DD);
                const float4 e0 = e[0], e1 = e[1], e2 = e[2], e3 = e[3];
                const float4 a0 = sA[s][0], a1 = sA[s][1], a2 = sA[s][2], a3 = sA[s][3];
                float d2 = 0.f;
                d2 = __fmaf_rn(e0.x - a0.x, e0.x - a0.x, d2);
                d2 = __fmaf_rn(e0.y - a0.y, e0.y - a0.y, d2);
                d2 = __fmaf_rn(e0.z - a0.z, e0.z - a0.z, d2);
                d2 = __fmaf_rn(e0.w - a0.w, e0.w - a0.w, d2);
                d2 = __fmaf_rn(e1.x - a1.x, e1.x - a1.x, d2);
                d2 = __fmaf_rn(e1.y - a1.y, e1.y - a1.y, d2);
                d2 = __fmaf_rn(e1.z - a1.z, e1.z - a1.z, d2);
                d2 = __fmaf_rn(e1.w - a1.w, e1.w - a1.w, d2);
                d2 = __fmaf_rn(e2.x - a2.x, e2.x - a2.x, d2);
                d2 = __fmaf_rn(e2.y - a2.y, e2.y - a2.y, d2);
                d2 = __fmaf_rn(e2.z - a2.z, e2.z - a2.z, d2);
                d2 = __fmaf_rn(e2.w - a2.w, e2.w - a2.w, d2);
                d2 = __fmaf_rn(e3.x - a3.x, e3.x - a3.x, d2);
                d2 = __fmaf_rn(e3.y - a3.y, e3.y - a3.y, d2);
                d2 = __fmaf_rn(e3.z - a3.z, e3.z - a3.z, d2);
                d2 = __fmaf_rn(e3.w - a3.w, e3.w - a3.w, d2);
                atomicAdd(&spack[s], (1ull << 44) + __float2ull_rn(d2 * 1048576.f));
            }
        }
        __syncthreads();
        if (tid < KK) {
            const unsigned long long v = spack[tid];
            if (v) {
                atomicAdd(&g_inst[b2][tid], (int)(v >> 44));
                const float ds = (float)(v & ((1ull << 44) - 1ull)) * (1.f / 1048576.f);
                if (ds != 0.f) atomicAdd(&g_sd2[b2][tid], ds);
            }
        }
    } else {
        // ================= PHASE 3: repulsion (blocks 280..295, 2 per event) =========
        const int idx  = blk - PB_BLOCKS;        // 0..15
        const int rb   = idx >> 1;               // event
        const int half = idx & 1;                // j-half
        const int Mv   = __ldcg(&g_Mv[rb]);
        const int msel = min(Mv, MMAX);
        const int jlo  = half * 512;
        const int jhi  = min(msel, jlo + 512);

        if (jlo < jhi) {
            const int mcol = min(Mv, CAP);
            for (int i = tid; i < CAP; i += NTHR)
                sidx[i] = (i < mcol) ? __ldcg(&g_cplist[rb][i]) : 0x7fffffff;
            __syncthreads();

            if (Mv > MMAX) {   // statistically never; correctness fallback
                for (int ksz = 2; ksz <= CAP; ksz <<= 1) {
                    for (int j = ksz >> 1; j > 0; j >>= 1) {
                        for (int i = tid; i < CAP; i += NTHR) {
                            int ixj = i ^ j;
                            if (ixj > i) {
                                bool up = ((i & ksz) == 0);
                                int a = sidx[i], c = sidx[ixj];
                                if ((a > c) == up) { sidx[i] = c; sidx[ixj] = a; }
                            }
                        }
                        __syncthreads();
                    }
                }
            }

            const size_t reb = (size_t)rb * NN;
            float acc = 0.f;

            for (int jt = jlo; jt < jhi; jt += RJT) {
                const int cnt = min(RJT, jhi - jt);
                __syncthreads();
                for (int t = tid; t < cnt * 4; t += NTHR) {
                    const int j = t >> 2, qq = t & 3;
                    reinterpret_cast<float4*>(sj)[t] =
                        reinterpret_cast<const float4*>(embed + (reb + sidx[jt + j]) * DD)[qq];
                }
                __syncthreads();

                for (int i = tid; i < msel; i += NTHR) {
                    float myE[DD];
                    const float4* er = reinterpret_cast<const float4*>(embed + (reb + sidx[i]) * DD);
                    #pragma unroll
                    for (int qq = 0; qq < 4; qq++) {
                        const float4 v = er[qq];
                        myE[qq * 4 + 0] = v.x; myE[qq * 4 + 1] = v.y;
                        myE[qq * 4 + 2] = v.z; myE[qq * 4 + 3] = v.w;
                    }
                    #pragma unroll 2
                    for (int j = 0; j < cnt; j++) {
                        float d2 = 0.f;
                        #pragma unroll
                        for (int d = 0; d < DD; d++) {
                            const float df = myE[d] - sj[j * DD + d];
                            d2 = __fmaf_rn(df, df, d2);
                        }
                        acc += __expf(-d2);
                    }
                }
            }

            #pragma unroll
            for (int off = 16; off; off >>= 1) acc += __shfl_down_sync(0xffffffff, acc, off);
            if ((tid & 31) == 0) red[tid >> 5] = acc;
            __syncthreads();
            if (tid == 0) {
                float tot = 0.f;
                #pragma unroll
                for (int w = 0; w < 16; w++) tot += red[w];
                atomicAdd(&g_rep[rb], tot);
            }
        }
    }

    grid_barrier(1);

    // ================= PHASE 4: finalize + reset (block 0 only) =================
    if (blk == 0) {
        const int lane = tid & 31;
        const int wid  = tid >> 5;

        __shared__ float s_loss[BB];
        __shared__ int   s_ok[BB];

        if (wid < BB) {
            const int e = wid;
            int   c[8], inst[8];
            float sf[8], sd[8];
            #pragma unroll
            for (int i = 0; i < 8; i++) {
                const int k = lane + i * 32;
                c[i]    = __ldcg(&g_cnt_cp[e][k]);
                inst[i] = __ldcg(&g_inst[e][k]);
                sf[i]   = __ldcg(&g_sum_f[e][k]);
                sd[i]   = __ldcg(&g_sd2[e][k]);
            }

            float w = 0.f, wf = 0.f, at = 0.f;
            #pragma unroll
            for (int i = 0; i < 8; i++) {
                if (c[i] > 0) {
                    const float fw = (float)inst[i];
                    w  += fw;
                    wf += fw * sf[i] / fmaxf((float)c[i], 1.f);
                    at += sd[i] / fmaxf((float)inst[i], 1.f);
                }
            }
            #pragma unroll
            for (int off = 16; off; off >>= 1) {
                w  += __shfl_down_sync(0xffffffff, w,  off);
                wf += __shfl_down_sync(0xffffffff, wf, off);
                at += __shfl_down_sync(0xffffffff, at, off);
            }

            if (lane == 0) {
                const float pos_bce = wf / fmaxf(w, 1.f);

                const float n_cp  = (float)__ldcg(&g_scal_i[e][0]);
                const float n_bg  = (float)__ldcg(&g_scal_i[e][1]);
                const float n_ncp = (float)NN - n_cp;
                const float n_val = (float)NN - n_bg;

                const float f0 = __ldcg(&g_scal_f[e][0]);
                const float f1 = __ldcg(&g_scal_f[e][1]);
                const float f2 = __ldcg(&g_scal_f[e][2]);
                const float f3 = __ldcg(&g_scal_f[e][3]);

                const float neg_bce    = (n_ncp > 0.f) ? f0 / fmaxf(n_ncp, 1.f) : 0.f;
                const float bg_bce     = (n_bg  > 0.f) ? f1 / fmaxf(n_bg,  1.f) : 0.f;
                const float pos_margin = f2 / fmaxf(n_cp, 1.f);
                const float neg_margin = (n_ncp > 0.f) ? f3 / fmaxf(n_ncp, 1.f) : 0.f;

                const float beta_loss = 10.f * pos_bce + 3.f * neg_bce + 6.f * bg_bce
                                      + 10.f * (pos_margin + neg_margin);

                const int   Mv = __ldcg(&g_Mv[e]);
                const float fM = (float)Mv;
                const float rep_term = (Mv > 1) ? __ldcg(&g_rep[e]) / fmaxf(fM * fM, 1.f) : 0.f;

                s_loss[e] = beta_loss + at + rep_term;
                s_ok[e]   = (n_val > 0.f) && (Mv > 0);
            }
        }
        __syncthreads();

        if (tid == 0) {
            float total = 0.f, cnt = 0.f;
            #pragma unroll
            for (int e = 0; e < BB; e++)
                if (s_ok[e]) { total += s_loss[e]; cnt += 1.f; }
            out[0] = (cnt > 0.f) ? total / fmaxf(cnt, 1.f) : 0.f;
        }
        __syncthreads();

        // reset all scratch so the graph replays deterministically
        for (int t = tid; t < BB * KK; t += NTHR) {
            const int e = t >> 8, k = t & 255;
            g_sum_f[e][k]  = 0.f;
            g_cnt_cp[e][k] = 0;
            g_inst[e][k]   = 0;
            g_first[e][k]  = 0;
            g_sd2[e][k]    = 0.f;
        }
        if (tid < BB) {
            g_Mv[tid]  = 0;
            g_rep[tid] = 0.f;
            #pragma unroll
            for (int j = 0; j < 4; j++) g_scal_f[tid][j] = 0.f;
            g_scal_i[tid][0] = 0; g_scal_i[tid][1] = 0;
        }
    }
}

// ---------------- launch: ONE persistent kernel, occ 2 ----------------
extern "C" void kernel_launch(void* const* d_in, const int* in_sizes, int n_in,
                              void* d_out, int out_size)
{
    (void)in_sizes; (void)n_in; (void)out_size;
    const float* beta  = (const float*)d_in[0];
    const float* embed = (const float*)d_in[1];
    const int*   sid   = (const int*)d_in[2];
    const int*   cp    = (const int*)d_in[3];

    fused_all_kernel<<<GRID, NTHR>>>(beta, embed, sid, cp, (float*)d_out);
}